// round 3
// baseline (speedup 1.0000x reference)
#include <cuda_runtime.h>

#define L    4096
#define NK   40
#define DIN  64
#define DOUT 64

// Scratch (static device arrays; no allocation anywhere)
__device__ float g_phiT[NK * L];           // phi transposed: [k][t]
__device__ float g_Zp[NK * L * 128];       // [k][s][b*64+o]
__device__ float g_Zm[NK * L * 128];       // [k][s][b*64+o], includes sgn(s)

// ---------------------------------------------------------------------------
// phi (L,K) -> phiT (K,L)
__global__ void k_phiT(const float* __restrict__ phi) {
    int i = blockIdx.x * 256 + threadIdx.x;
    if (i < L * NK) {
        int t = i / NK, k = i % NK;
        g_phiT[k * L + t] = phi[i];
    }
}

// ---------------------------------------------------------------------------
// Autoregressive term, writes (initializes) out:
// out[b,t,o] = sum_{i<3, t-i>=0} sum_d x[b,t-i,d] * M[o,d,i]
__global__ void k_ar(const float* __restrict__ x, const float* __restrict__ M,
                     float* __restrict__ out) {
    __shared__ float sM[3 * 64 * 64];   // sM[(i*64+d)*64 + o]
    for (int idx = threadIdx.x; idx < 64 * 64 * 3; idx += 256) {
        int o = idx / 192, rem = idx % 192, d = rem / 3, i = rem % 3;
        sM[(i * 64 + d) * 64 + o] = M[idx];
    }
    __syncthreads();
    int gid = blockIdx.x * 256 + threadIdx.x;      // over 2*4096*64
    int o = gid & 63;
    int t = (gid >> 6) & (L - 1);
    int b = gid >> 18;
    float acc = 0.f;
    for (int i = 0; i < 3; i++) {
        int tt = t - i;
        if (tt < 0) break;
        const float* xr = x + (((b << 12) + tt) << 6);
        const float* mr = sM + i * 4096;
        #pragma unroll 16
        for (int d = 0; d < 64; d++) acc += xr[d] * mr[d * 64 + o];
    }
    out[gid] = acc;
}

// ---------------------------------------------------------------------------
// Z build: for each k, b:  Zp[k,s,bo] = sum_d x[b,s,d]*Mp[k,d,o]
//                          Zm[k,s,bo] = sgn(s) * sum_d x[b,s,d]*Mm[k,d,o]
// grid (64 s-tiles, 2 b, 40 k), block 256
__global__ void k_z(const float* __restrict__ x, const float* __restrict__ Mp,
                    const float* __restrict__ Mm) {
    __shared__ float sx[64][64];
    __shared__ float sM[64][64];
    int st = blockIdx.x, b = blockIdx.y, k = blockIdx.z;
    int tid = threadIdx.x, tx = tid & 15, ty = tid >> 4;
    int sbase = st * 64;

    const float* xb = x + (((b << 12) + sbase) << 6);
    for (int i = tid; i < 4096; i += 256) sx[i >> 6][i & 63] = xb[i];
    const float* mp = Mp + (k << 12);
    for (int i = tid; i < 4096; i += 256) sM[i >> 6][i & 63] = mp[i];
    __syncthreads();

    float accP[4][4] = {};
    #pragma unroll 8
    for (int kk = 0; kk < 64; kk++) {
        float a[4];
        #pragma unroll
        for (int i = 0; i < 4; i++) a[i] = sx[ty * 4 + i][kk];
        float4 bv = *(float4*)&sM[kk][tx * 4];
        #pragma unroll
        for (int i = 0; i < 4; i++) {
            accP[i][0] += a[i] * bv.x; accP[i][1] += a[i] * bv.y;
            accP[i][2] += a[i] * bv.z; accP[i][3] += a[i] * bv.w;
        }
    }
    __syncthreads();

    const float* mm = Mm + (k << 12);
    for (int i = tid; i < 4096; i += 256) sM[i >> 6][i & 63] = mm[i];
    __syncthreads();

    float accM[4][4] = {};
    #pragma unroll 8
    for (int kk = 0; kk < 64; kk++) {
        float a[4];
        #pragma unroll
        for (int i = 0; i < 4; i++) a[i] = sx[ty * 4 + i][kk];
        float4 bv = *(float4*)&sM[kk][tx * 4];
        #pragma unroll
        for (int i = 0; i < 4; i++) {
            accM[i][0] += a[i] * bv.x; accM[i][1] += a[i] * bv.y;
            accM[i][2] += a[i] * bv.z; accM[i][3] += a[i] * bv.w;
        }
    }

    #pragma unroll
    for (int i = 0; i < 4; i++) {
        int r = sbase + ty * 4 + i;
        float sg = (r & 1) ? -1.f : 1.f;
        int base = ((k << 12) + r) * 128 + (b << 6) + tx * 4;
        float4 vp = make_float4(accP[i][0], accP[i][1], accP[i][2], accP[i][3]);
        float4 vm = make_float4(sg * accM[i][0], sg * accM[i][1],
                                sg * accM[i][2], sg * accM[i][3]);
        *(float4*)&g_Zp[base] = vp;
        *(float4*)&g_Zm[base] = vm;
    }
}

// ---------------------------------------------------------------------------
// Causal Toeplitz conv + accumulate:
// out[b,t,o] += sum_{s<=t} phi_k[t-s] * (Zp[k,s,bo] + sgn(t)*Zm[k,s,bo])
// grid (64 row-tiles, 2 col-tiles, 40 k), block 256 (16x16), 4x4 per thread/branch
__global__ void k_conv(float* __restrict__ out) {
    __shared__ float sZp[64][64];
    __shared__ float sZm[64][64];
    __shared__ float sPhi[128];
    int rt = blockIdx.x, ct = blockIdx.y, k = blockIdx.z;
    int tid = threadIdx.x, tx = tid & 15, ty = tid >> 4;
    const float* phik = g_phiT + (k << 12);

    float accP[4][4] = {};
    float accM[4][4] = {};

    for (int j = 0; j <= rt; j++) {
        int Dd = (rt - j) * 64;                  // rowbase - sbase
        if (tid < 127) {
            int idx = Dd - 63 + tid;
            sPhi[tid] = (idx >= 0) ? phik[idx] : 0.f;
        }
        int sbase = j * 64;
        const float* zp = g_Zp + ((k << 12) + sbase) * 128 + (ct << 6);
        const float* zm = g_Zm + ((k << 12) + sbase) * 128 + (ct << 6);
        for (int i2 = tid; i2 < 1024; i2 += 256) {
            int r = i2 >> 4, c4 = (i2 & 15) << 2;
            *(float4*)&sZp[r][c4] = *(const float4*)(zp + r * 128 + c4);
            *(float4*)&sZm[r][c4] = *(const float4*)(zm + r * 128 + c4);
        }
        __syncthreads();

        #pragma unroll 4
        for (int kk = 0; kk < 64; kk++) {
            float a[4];
            #pragma unroll
            for (int i = 0; i < 4; i++) a[i] = sPhi[ty * 4 + i - kk + 63];
            float4 bp = *(float4*)&sZp[kk][tx * 4];
            float4 bm = *(float4*)&sZm[kk][tx * 4];
            #pragma unroll
            for (int i = 0; i < 4; i++) {
                accP[i][0] += a[i] * bp.x; accP[i][1] += a[i] * bp.y;
                accP[i][2] += a[i] * bp.z; accP[i][3] += a[i] * bp.w;
                accM[i][0] += a[i] * bm.x; accM[i][1] += a[i] * bm.y;
                accM[i][2] += a[i] * bm.z; accM[i][3] += a[i] * bm.w;
            }
        }
        __syncthreads();
    }

    int colbase = ct << 6;
    #pragma unroll
    for (int i = 0; i < 4; i++) {
        int r = rt * 64 + ty * 4 + i;
        float sg = (r & 1) ? -1.f : 1.f;
        #pragma unroll
        for (int jj = 0; jj < 4; jj++) {
            int c = colbase + tx * 4 + jj;
            int b = c >> 6, o = c & 63;
            atomicAdd(&out[(((b << 12) + r) << 6) + o], accP[i][jj] + sg * accM[i][jj]);
        }
    }
}

// ---------------------------------------------------------------------------
extern "C" void kernel_launch(void* const* d_in, const int* in_sizes, int n_in,
                              void* d_out, int out_size) {
    const float* x   = (const float*)d_in[0];   // (2,4096,64)
    const float* phi = (const float*)d_in[1];   // (4096,40)
    const float* M   = (const float*)d_in[2];   // (64,64,3)
    const float* Mp  = (const float*)d_in[3];   // (40,64,64)
    const float* Mm  = (const float*)d_in[4];   // (40,64,64)
    float* out = (float*)d_out;                 // (2,4096,64)

    k_phiT<<<(L * NK + 255) / 256, 256>>>(phi);
    k_ar<<<(2 * L * 64) / 256, 256>>>(x, M, out);          // writes out (AR base)
    k_z<<<dim3(64, 2, NK), 256>>>(x, Mp, Mm);
    k_conv<<<dim3(64, 2, NK), 256>>>(out);                 // accumulates spectral part
}

// round 8
// speedup vs baseline: 1.7156x; 1.7156x over previous
#include <cuda_runtime.h>
#include <cuda_bf16.h>

#define L    4096
#define NK   40

// ---------------------------------------------------------------------------
// Global scratch (static; no allocations)
__device__ unsigned g_phiP [NK * L];              // packed bf16 hi|lo<<16 of phi[lag]
__device__ unsigned g_phiSP[NK * L];              // same for (-1)^lag * phi[lag]
__device__ unsigned g_BP[NK * 2 * 128 * L];       // [k][br][n][s] packed Z^T (br0=Zp, br1=Zm_raw)

// ---------------------------------------------------------------------------
__device__ __forceinline__ unsigned smem_u32(const void* p) {
    unsigned a;
    asm("{ .reg .u64 t; cvta.to.shared.u64 t, %1; cvt.u32.u64 %0, t; }" : "=r"(a) : "l"(p));
    return a;
}
__device__ __forceinline__ unsigned packbf(float v) {
    __nv_bfloat16 h = __float2bfloat16(v);
    float r = v - __bfloat162float(h);
    __nv_bfloat16 l = __float2bfloat16(r);
    return (unsigned)__bfloat16_as_ushort(h) | ((unsigned)__bfloat16_as_ushort(l) << 16);
}
__device__ __forceinline__ void ldsm4(unsigned& r0, unsigned& r1, unsigned& r2,
                                      unsigned& r3, unsigned addr) {
    asm volatile("ldmatrix.sync.aligned.m8n8.x4.shared.b16 {%0,%1,%2,%3}, [%4];"
                 : "=r"(r0), "=r"(r1), "=r"(r2), "=r"(r3) : "r"(addr));
}
__device__ __forceinline__ void hmma(float* c, unsigned a0, unsigned a1, unsigned a2,
                                     unsigned a3, unsigned b0, unsigned b1) {
    asm volatile(
        "mma.sync.aligned.m16n8k16.row.col.f32.bf16.bf16.f32 "
        "{%0,%1,%2,%3},{%4,%5,%6,%7},{%8,%9},{%0,%1,%2,%3};"
        : "+f"(c[0]), "+f"(c[1]), "+f"(c[2]), "+f"(c[3])
        : "r"(a0), "r"(a1), "r"(a2), "r"(a3), "r"(b0), "r"(b1));
}

// ---------------------------------------------------------------------------
// phi prep: packed bf16 split for phi[lag] and (-1)^lag*phi[lag], [k][lag]
__global__ void k_prep(const float* __restrict__ phi) {
    int gid = blockIdx.x * 256 + threadIdx.x;
    if (gid >= NK * L) return;
    int k = gid >> 12, lag = gid & (L - 1);
    float v = phi[lag * NK + k];
    g_phiP[(k << 12) + lag] = packbf(v);
    g_phiSP[(k << 12) + lag] = packbf((lag & 1) ? -v : v);
}

// ---------------------------------------------------------------------------
// AR term (initializes out)
__global__ void k_ar(const float* __restrict__ x, const float* __restrict__ M,
                     float* __restrict__ out) {
    __shared__ float sM[3 * 64 * 64];
    for (int idx = threadIdx.x; idx < 64 * 64 * 3; idx += 256) {
        int o = idx / 192, rem = idx % 192, d = rem / 3, i = rem % 3;
        sM[(i * 64 + d) * 64 + o] = M[idx];
    }
    __syncthreads();
    int gid = blockIdx.x * 256 + threadIdx.x;
    int o = gid & 63;
    int t = (gid >> 6) & (L - 1);
    int b = gid >> 18;
    float acc = 0.f;
    for (int i = 0; i < 3; i++) {
        int tt = t - i;
        if (tt < 0) break;
        const float* xr = x + (((b << 12) + tt) << 6);
        const float* mr = sM + i * 4096;
        #pragma unroll 16
        for (int d = 0; d < 64; d++) acc += xr[d] * mr[d * 64 + o];
    }
    out[gid] = acc;
}

// ---------------------------------------------------------------------------
// Z build: Zp[s,n] = x[b,s,:]·Mp[k,:,o], Zm_raw[s,n] = x[b,s,:]·Mm[k,:,o]
// written transposed & bf16-split-packed into g_BP[k][br][n][s]
__global__ void k_z(const float* __restrict__ x, const float* __restrict__ Mp,
                    const float* __restrict__ Mm) {
    __shared__ float sx[64][64];
    __shared__ float sM[64][64];
    int st = blockIdx.x, b = blockIdx.y, k = blockIdx.z;
    int tid = threadIdx.x, tx = tid & 15, ty = tid >> 4;
    int sbase = st * 64;

    const float* xb = x + (((b << 12) + sbase) << 6);
    for (int i = tid; i < 4096; i += 256) sx[i >> 6][i & 63] = xb[i];
    const float* mp = Mp + (k << 12);
    for (int i = tid; i < 4096; i += 256) sM[i >> 6][i & 63] = mp[i];
    __syncthreads();

    float accP[4][4] = {};
    #pragma unroll 8
    for (int kk = 0; kk < 64; kk++) {
        float a[4];
        #pragma unroll
        for (int i = 0; i < 4; i++) a[i] = sx[ty * 4 + i][kk];
        float4 bv = *(float4*)&sM[kk][tx * 4];
        #pragma unroll
        for (int i = 0; i < 4; i++) {
            accP[i][0] += a[i] * bv.x; accP[i][1] += a[i] * bv.y;
            accP[i][2] += a[i] * bv.z; accP[i][3] += a[i] * bv.w;
        }
    }
    __syncthreads();

    const float* mm = Mm + (k << 12);
    for (int i = tid; i < 4096; i += 256) sM[i >> 6][i & 63] = mm[i];
    __syncthreads();

    float accM[4][4] = {};
    #pragma unroll 8
    for (int kk = 0; kk < 64; kk++) {
        float a[4];
        #pragma unroll
        for (int i = 0; i < 4; i++) a[i] = sx[ty * 4 + i][kk];
        float4 bv = *(float4*)&sM[kk][tx * 4];
        #pragma unroll
        for (int i = 0; i < 4; i++) {
            accM[i][0] += a[i] * bv.x; accM[i][1] += a[i] * bv.y;
            accM[i][2] += a[i] * bv.z; accM[i][3] += a[i] * bv.w;
        }
    }

    int srow = sbase + ty * 4;
    #pragma unroll
    for (int j = 0; j < 4; j++) {
        int n = (b << 6) + tx * 4 + j;
        uint4 vp, vm;
        vp.x = packbf(accP[0][j]); vp.y = packbf(accP[1][j]);
        vp.z = packbf(accP[2][j]); vp.w = packbf(accP[3][j]);
        vm.x = packbf(accM[0][j]); vm.y = packbf(accM[1][j]);
        vm.z = packbf(accM[2][j]); vm.w = packbf(accM[3][j]);
        *(uint4*)&g_BP[((size_t)(k * 2 + 0) * 128 + n) * 4096 + srow] = vp;
        *(uint4*)&g_BP[((size_t)(k * 2 + 1) * 128 + n) * 4096 + srow] = vm;
    }
}

// ---------------------------------------------------------------------------
// Warp-MMA (HMMA) Toeplitz GEMM. One CTA = (128-row t-tile, filter k).
// C[128,128] fp32 in registers (8 warps x 64x32), K accumulated over s-chunks
// and both branches. bf16 hi/lo split: hh + hl + lh.
// SMEM rows padded to 144B -> conflict-free ldmatrix without XOR swizzle.
#define ROWB    144        // bytes per smem tile row (64 bf16 + 8 pad)
#define OFF_WIN 0
#define OFF_AH  768
#define OFF_AL  (OFF_AH + 128 * ROWB)
#define OFF_BH  (OFF_AL + 128 * ROWB)
#define OFF_BL  (OFF_BH + 128 * ROWB)
#define SMEM_TOTAL (OFF_BL + 128 * ROWB)

__global__ void __launch_bounds__(256) k_gemm(float* __restrict__ out) {
    extern __shared__ char smem[];
    unsigned sbu = smem_u32(smem);
    int tid = threadIdx.x, wid = tid >> 5, lane = tid & 31;
    int rt = blockIdx.x, k = blockIdx.y;
    int rowbase = rt << 7;

    int mg = wid >> 2, ng = wid & 3;   // warp tile: rows [mg*64,+64), cols [ng*32,+32)

    // per-lane ldmatrix address offsets
    unsigned aLane = (unsigned)((mg * 64 + (lane & 15)) * ROWB + (lane >> 4) * 16);
    unsigned bLane = (unsigned)((ng * 32 + (lane & 7) + ((lane >> 4) & 1) * 8) * ROWB
                                + ((lane >> 3) & 1) * 16);
    unsigned aH = sbu + OFF_AH + aLane, aL = sbu + OFF_AL + aLane;
    unsigned bH = sbu + OFF_BH + bLane, bL = sbu + OFF_BL + bLane;

    unsigned* win = (unsigned*)smem;

    float c[4][4][4];
    #pragma unroll
    for (int i = 0; i < 4; i++)
        #pragma unroll
        for (int j = 0; j < 4; j++)
            #pragma unroll
            for (int q = 0; q < 4; q++) c[i][j][q] = 0.f;

    int nchunks = 2 * (rt + 1);
    int am = tid >> 1, ah2 = tid & 1;          // A-build: row, k-half

    for (int br = 0; br < 2; br++) {
        const unsigned* phiArr = (br ? g_phiSP : g_phiP) + (k << 12);
        const unsigned* Bbase = g_BP + (size_t)(k * 2 + br) * 128 * 4096;

        for (int sbk = 0; sbk < nchunks; sbk++) {
            int sbase = sbk << 6;
            int Dd = rowbase - sbase;

            // stage phi window phi[Dd-63 .. Dd+128]
            if (tid < 192) {
                int lag = Dd - 63 + tid;
                win[tid] = (lag >= 0 && lag < L) ? phiArr[lag] : 0u;
            }
            __syncthreads();

            // build A tiles: A[m][kk] = phi[Dd+m-kk] -> win[m-kk+63]
            {
                char* Ah = smem + OFF_AH + am * ROWB;
                char* Al = smem + OFF_AL + am * ROWB;
                int base = am + 63 - ah2 * 32;
                #pragma unroll
                for (int j = 0; j < 16; j++) {
                    int kk = ah2 * 32 + 2 * j;
                    unsigned P0 = win[base - 2 * j];
                    unsigned P1 = win[base - 2 * j - 1];
                    *(unsigned*)(Ah + kk * 2) = (P0 & 0xffffu) | (P1 << 16);
                    *(unsigned*)(Al + kk * 2) = (P0 >> 16) | (P1 & 0xffff0000u);
                }
            }
            // build B tiles: B[n][kk] = Z^T[n][sbase+kk]
            {
                char* Bh = smem + OFF_BH + am * ROWB;
                char* Bl = smem + OFF_BL + am * ROWB;
                const uint4* src = (const uint4*)(Bbase + (size_t)am * 4096 + sbase + ah2 * 32);
                #pragma unroll
                for (int q = 0; q < 8; q++) {
                    uint4 v = src[q];
                    int kb = (ah2 * 32 + q * 4) * 2;
                    *(unsigned*)(Bh + kb)     = (v.x & 0xffffu) | (v.y << 16);
                    *(unsigned*)(Bh + kb + 4) = (v.z & 0xffffu) | (v.w << 16);
                    *(unsigned*)(Bl + kb)     = (v.x >> 16) | (v.y & 0xffff0000u);
                    *(unsigned*)(Bl + kb + 4) = (v.z >> 16) | (v.w & 0xffff0000u);
                }
            }
            __syncthreads();

            // MMA phase: 4 k-steps of 16
            #pragma unroll
            for (int ks = 0; ks < 4; ks++) {
                unsigned ko = ks * 32;   // byte offset of k-step
                unsigned Ahr[4][4], Alr[4][4], Bhr[2][4], Blr[2][4];
                #pragma unroll
                for (int mt = 0; mt < 4; mt++) {
                    ldsm4(Ahr[mt][0], Ahr[mt][1], Ahr[mt][2], Ahr[mt][3],
                          aH + mt * (16 * ROWB) + ko);
                    ldsm4(Alr[mt][0], Alr[mt][1], Alr[mt][2], Alr[mt][3],
                          aL + mt * (16 * ROWB) + ko);
                }
                #pragma unroll
                for (int p = 0; p < 2; p++) {
                    ldsm4(Bhr[p][0], Bhr[p][1], Bhr[p][2], Bhr[p][3],
                          bH + p * (16 * ROWB) + ko);
                    ldsm4(Blr[p][0], Blr[p][1], Blr[p][2], Blr[p][3],
                          bL + p * (16 * ROWB) + ko);
                }
                #pragma unroll
                for (int mt = 0; mt < 4; mt++) {
                    #pragma unroll
                    for (int nt = 0; nt < 4; nt++) {
                        int p = nt >> 1, i0 = (nt & 1) * 2;
                        hmma(c[mt][nt], Ahr[mt][0], Ahr[mt][1], Ahr[mt][2], Ahr[mt][3],
                             Bhr[p][i0], Bhr[p][i0 + 1]);
                        hmma(c[mt][nt], Ahr[mt][0], Ahr[mt][1], Ahr[mt][2], Ahr[mt][3],
                             Blr[p][i0], Blr[p][i0 + 1]);
                        hmma(c[mt][nt], Alr[mt][0], Alr[mt][1], Alr[mt][2], Alr[mt][3],
                             Bhr[p][i0], Bhr[p][i0 + 1]);
                    }
                }
            }
            __syncthreads();
        }
    }

    // epilogue: atomicAdd fragments onto AR base
    int g = lane >> 2, tq = lane & 3;
    #pragma unroll
    for (int mt = 0; mt < 4; mt++) {
        #pragma unroll
        for (int nt = 0; nt < 4; nt++) {
            int row = rowbase + mg * 64 + mt * 16 + g;
            int col = ng * 32 + nt * 8 + 2 * tq;
            int b = col >> 6, o = col & 63;
            float* p0 = out + (((size_t)b * 4096 + row) * 64 + o);
            atomicAdd(p0,            c[mt][nt][0]);
            atomicAdd(p0 + 1,        c[mt][nt][1]);
            atomicAdd(p0 + 8 * 64,   c[mt][nt][2]);
            atomicAdd(p0 + 8 * 64 + 1, c[mt][nt][3]);
        }
    }
}

// ---------------------------------------------------------------------------
extern "C" void kernel_launch(void* const* d_in, const int* in_sizes, int n_in,
                              void* d_out, int out_size) {
    const float* x   = (const float*)d_in[0];   // (2,4096,64)
    const float* phi = (const float*)d_in[1];   // (4096,40)
    const float* M   = (const float*)d_in[2];   // (64,64,3)
    const float* Mp  = (const float*)d_in[3];   // (40,64,64)
    const float* Mm  = (const float*)d_in[4];   // (40,64,64)
    float* out = (float*)d_out;                 // (2,4096,64)

    cudaFuncSetAttribute(k_gemm, cudaFuncAttributeMaxDynamicSharedMemorySize, SMEM_TOTAL);

    k_prep<<<(NK * L + 255) / 256, 256>>>(phi);
    k_ar<<<(2 * L * 64) / 256, 256>>>(x, M, out);
    k_z<<<dim3(64, 2, NK), 256>>>(x, Mp, Mm);
    k_gemm<<<dim3(32, NK), 256, SMEM_TOTAL>>>(out);
}

// round 9
// speedup vs baseline: 3.0970x; 1.8052x over previous
#include <cuda_runtime.h>
#include <cuda_fp16.h>

#define L    4096
#define NK   40

// ---------------------------------------------------------------------------
// Global scratch (static; no allocations)
__device__ unsigned g_phiP [NK * L];     // packed fp16 hi | lo<<16 of phi[lag]
__device__ unsigned g_phiSP[NK * L];     // same for (-1)^lag * phi[lag]
__device__ __half   g_B[(size_t)NK * 2 * 128 * L];  // [k][br][n][s] fp16 Z^T

// ---------------------------------------------------------------------------
__device__ __forceinline__ unsigned smem_u32(const void* p) {
    unsigned a;
    asm("{ .reg .u64 t; cvta.to.shared.u64 t, %1; cvt.u32.u64 %0, t; }" : "=r"(a) : "l"(p));
    return a;
}
__device__ __forceinline__ unsigned packhf(float v) {
    __half h = __float2half_rn(v);
    float r = v - __half2float(h);
    __half l = __float2half_rn(r);
    return (unsigned)__half_as_ushort(h) | ((unsigned)__half_as_ushort(l) << 16);
}
__device__ __forceinline__ void ldsm4(unsigned& r0, unsigned& r1, unsigned& r2,
                                      unsigned& r3, unsigned addr) {
    asm volatile("ldmatrix.sync.aligned.m8n8.x4.shared.b16 {%0,%1,%2,%3}, [%4];"
                 : "=r"(r0), "=r"(r1), "=r"(r2), "=r"(r3) : "r"(addr));
}
__device__ __forceinline__ void hmma(float* c, unsigned a0, unsigned a1, unsigned a2,
                                     unsigned a3, unsigned b0, unsigned b1) {
    asm volatile(
        "mma.sync.aligned.m16n8k16.row.col.f32.f16.f16.f32 "
        "{%0,%1,%2,%3},{%4,%5,%6,%7},{%8,%9},{%0,%1,%2,%3};"
        : "+f"(c[0]), "+f"(c[1]), "+f"(c[2]), "+f"(c[3])
        : "r"(a0), "r"(a1), "r"(a2), "r"(a3), "r"(b0), "r"(b1));
}
__device__ __forceinline__ void cp16(unsigned dst, const void* src) {
    asm volatile("cp.async.ca.shared.global [%0], [%1], 16;" :: "r"(dst), "l"(src));
}

// ---------------------------------------------------------------------------
// phi prep
__global__ void k_prep(const float* __restrict__ phi) {
    int gid = blockIdx.x * 256 + threadIdx.x;
    if (gid >= NK * L) return;
    int k = gid >> 12, lag = gid & (L - 1);
    float v = phi[lag * NK + k];
    g_phiP[(k << 12) + lag] = packhf(v);
    g_phiSP[(k << 12) + lag] = packhf((lag & 1) ? -v : v);
}

// ---------------------------------------------------------------------------
// AR term (initializes out)
__global__ void k_ar(const float* __restrict__ x, const float* __restrict__ M,
                     float* __restrict__ out) {
    __shared__ float sM[3 * 64 * 64];
    for (int idx = threadIdx.x; idx < 64 * 64 * 3; idx += 256) {
        int o = idx / 192, rem = idx % 192, d = rem / 3, i = rem % 3;
        sM[(i * 64 + d) * 64 + o] = M[idx];
    }
    __syncthreads();
    int gid = blockIdx.x * 256 + threadIdx.x;
    int o = gid & 63;
    int t = (gid >> 6) & (L - 1);
    int b = gid >> 18;
    float acc = 0.f;
    for (int i = 0; i < 3; i++) {
        int tt = t - i;
        if (tt < 0) break;
        const float* xr = x + (((b << 12) + tt) << 6);
        const float* mr = sM + i * 4096;
        #pragma unroll 16
        for (int d = 0; d < 64; d++) acc += xr[d] * mr[d * 64 + o];
    }
    out[gid] = acc;
}

// ---------------------------------------------------------------------------
// Z build (fp32 math), output single fp16 transposed [k][br][n][s]
__global__ void k_z(const float* __restrict__ x, const float* __restrict__ Mp,
                    const float* __restrict__ Mm) {
    __shared__ float sx[64][64];
    __shared__ float sM[64][64];
    int st = blockIdx.x, b = blockIdx.y, k = blockIdx.z;
    int tid = threadIdx.x, tx = tid & 15, ty = tid >> 4;
    int sbase = st * 64;

    const float* xb = x + (((b << 12) + sbase) << 6);
    for (int i = tid; i < 4096; i += 256) sx[i >> 6][i & 63] = xb[i];
    const float* mp = Mp + (k << 12);
    for (int i = tid; i < 4096; i += 256) sM[i >> 6][i & 63] = mp[i];
    __syncthreads();

    float accP[4][4] = {};
    #pragma unroll 8
    for (int kk = 0; kk < 64; kk++) {
        float a[4];
        #pragma unroll
        for (int i = 0; i < 4; i++) a[i] = sx[ty * 4 + i][kk];
        float4 bv = *(float4*)&sM[kk][tx * 4];
        #pragma unroll
        for (int i = 0; i < 4; i++) {
            accP[i][0] += a[i] * bv.x; accP[i][1] += a[i] * bv.y;
            accP[i][2] += a[i] * bv.z; accP[i][3] += a[i] * bv.w;
        }
    }
    __syncthreads();

    const float* mm = Mm + (k << 12);
    for (int i = tid; i < 4096; i += 256) sM[i >> 6][i & 63] = mm[i];
    __syncthreads();

    float accM[4][4] = {};
    #pragma unroll 8
    for (int kk = 0; kk < 64; kk++) {
        float a[4];
        #pragma unroll
        for (int i = 0; i < 4; i++) a[i] = sx[ty * 4 + i][kk];
        float4 bv = *(float4*)&sM[kk][tx * 4];
        #pragma unroll
        for (int i = 0; i < 4; i++) {
            accM[i][0] += a[i] * bv.x; accM[i][1] += a[i] * bv.y;
            accM[i][2] += a[i] * bv.z; accM[i][3] += a[i] * bv.w;
        }
    }

    int srow = sbase + ty * 4;
    #pragma unroll
    for (int j = 0; j < 4; j++) {
        int n = (b << 6) + tx * 4 + j;
        __half2 p01 = __floats2half2_rn(accP[0][j], accP[1][j]);
        __half2 p23 = __floats2half2_rn(accP[2][j], accP[3][j]);
        __half2 m01 = __floats2half2_rn(accM[0][j], accM[1][j]);
        __half2 m23 = __floats2half2_rn(accM[2][j], accM[3][j]);
        uint2 vp = make_uint2(*(unsigned*)&p01, *(unsigned*)&p23);
        uint2 vm = make_uint2(*(unsigned*)&m01, *(unsigned*)&m23);
        *(uint2*)&g_B[((size_t)(k * 2 + 0) * 128 + n) * 4096 + srow] = vp;
        *(uint2*)&g_B[((size_t)(k * 2 + 1) * 128 + n) * 4096 + srow] = vm;
    }
}

// ---------------------------------------------------------------------------
// HMMA Toeplitz GEMM, fp16 2-product (A split hi/lo, B single), cp.async
// double-buffered B, in-smem A build, paired row-tiles for load balance.
// CTA = (pair pid -> tiles {pid, 31-pid}, branch br, filter k). 8 warps 4x2.
#define ROWB     144
#define TILEB    (128 * ROWB)          // 18432
#define OFF_A    768                   // 4 tiles: [buf][h/l]
#define OFF_B    (OFF_A + 4 * TILEB)   // 2 tiles: [buf]
#define SMEM_TOTAL (OFF_B + 2 * TILEB) // 111360

__global__ void __launch_bounds__(256, 2) k_gemm(float* __restrict__ out) {
    extern __shared__ char smem[];
    unsigned sbu = smem_u32(smem);
    int tid = threadIdx.x, wid = tid >> 5, lane = tid & 31;
    int pid = blockIdx.x, br = blockIdx.y, k = blockIdx.z;
    int mg = wid >> 1, ng = wid & 1;   // warp tile: rows [mg*32,+32), cols [ng*64,+64)

    const unsigned* phiArr = (br ? g_phiSP : g_phiP) + (k << 12);
    const char* Bsrc = (const char*)(g_B + (size_t)(k * 2 + br) * 128 * 4096);

    unsigned aLaneOff = (unsigned)((mg * 32 + (lane & 15)) * ROWB + (lane >> 4) * 16);
    unsigned bLaneOff = (unsigned)((ng * 64 + (lane & 7) + ((lane >> 4) & 1) * 8) * ROWB
                                   + ((lane >> 3) & 1) * 16);
    unsigned* win = (unsigned*)smem;

    // B copy assignment: thread -> row (tid>>1), 4x16B at seg (tid&1)*64
    int crow = tid >> 1;
    int cseg = (tid & 1) * 64;
    size_t crowByte = (size_t)crow * 8192;
    unsigned cdstBase = sbu + OFF_B + crow * ROWB + cseg;

    int am = tid >> 1, ah2 = tid & 1;  // A build: row, kk-half
    int wbase = am + 63 - ah2 * 32;

    for (int ti = 0; ti < 2; ti++) {
        int rt = ti ? (31 - pid) : pid;
        int rowbase = rt << 7;
        int nch = 2 * (rt + 1);

        float c[2][8][4];
        #pragma unroll
        for (int i = 0; i < 2; i++)
            #pragma unroll
            for (int j = 0; j < 8; j++)
                #pragma unroll
                for (int q = 0; q < 4; q++) c[i][j][q] = 0.f;

        __syncthreads();   // guard smem reuse across tiles

        // prologue: prefetch B chunk 0 -> buf0
        {
            const char* src = Bsrc + crowByte + cseg;
            #pragma unroll
            for (int q = 0; q < 4; q++) cp16(cdstBase + q * 16, src + q * 16);
            asm volatile("cp.async.commit_group;");
        }

        for (int sbk = 0; sbk < nch; sbk++) {
            int p = sbk & 1;
            int Dd = rowbase - (sbk << 6);

            // stage phi window [Dd-63, Dd+128]
            if (tid < 192) {
                int lag = Dd - 63 + tid;
                win[tid] = (lag >= 0 && lag < L) ? phiArr[lag] : 0u;
            }
            __syncthreads();

            // build A tiles (hi, lo) into Abuf[p]: A[m][kk] = phi[Dd+m-kk]
            {
                char* Ah = smem + OFF_A + (p * 2 + 0) * TILEB + am * ROWB + ah2 * 64;
                char* Al = smem + OFF_A + (p * 2 + 1) * TILEB + am * ROWB + ah2 * 64;
                #pragma unroll
                for (int q = 0; q < 8; q++) {
                    unsigned P0 = win[wbase - 4 * q];
                    unsigned P1 = win[wbase - 4 * q - 1];
                    unsigned P2 = win[wbase - 4 * q - 2];
                    unsigned P3 = win[wbase - 4 * q - 3];
                    uint2 h, l;
                    h.x = (P0 & 0xffffu) | (P1 << 16);
                    h.y = (P2 & 0xffffu) | (P3 << 16);
                    l.x = (P0 >> 16) | (P1 & 0xffff0000u);
                    l.y = (P2 >> 16) | (P3 & 0xffff0000u);
                    *(uint2*)(Ah + q * 8) = h;
                    *(uint2*)(Al + q * 8) = l;
                }
            }

            asm volatile("cp.async.wait_group 0;");   // B[p] arrived
            __syncthreads();

            // prefetch next B chunk into buf[p^1] (overlaps MMA below)
            if (sbk + 1 < nch) {
                const char* src = Bsrc + crowByte + ((sbk + 1) << 7) + cseg;
                unsigned dst = cdstBase + (p ^ 1) * TILEB;
                #pragma unroll
                for (int q = 0; q < 4; q++) cp16(dst + q * 16, src + q * 16);
                asm volatile("cp.async.commit_group;");
            }

            // MMA phase: 4 k-steps of 16
            unsigned aH = sbu + OFF_A + (p * 2) * TILEB + aLaneOff;
            unsigned aL = aH + TILEB;
            unsigned bB = sbu + OFF_B + p * TILEB + bLaneOff;
            #pragma unroll
            for (int ks = 0; ks < 4; ks++) {
                unsigned ko = ks * 32;
                unsigned Ahr[2][4], Alr[2][4], Br[4][4];
                #pragma unroll
                for (int mt = 0; mt < 2; mt++) {
                    ldsm4(Ahr[mt][0], Ahr[mt][1], Ahr[mt][2], Ahr[mt][3],
                          aH + mt * (16 * ROWB) + ko);
                    ldsm4(Alr[mt][0], Alr[mt][1], Alr[mt][2], Alr[mt][3],
                          aL + mt * (16 * ROWB) + ko);
                }
                #pragma unroll
                for (int pg = 0; pg < 4; pg++)
                    ldsm4(Br[pg][0], Br[pg][1], Br[pg][2], Br[pg][3],
                          bB + pg * (16 * ROWB) + ko);
                #pragma unroll
                for (int mt = 0; mt < 2; mt++) {
                    #pragma unroll
                    for (int pg = 0; pg < 4; pg++) {
                        #pragma unroll
                        for (int hf = 0; hf < 2; hf++) {
                            hmma(c[mt][pg * 2 + hf],
                                 Ahr[mt][0], Ahr[mt][1], Ahr[mt][2], Ahr[mt][3],
                                 Br[pg][hf * 2], Br[pg][hf * 2 + 1]);
                            hmma(c[mt][pg * 2 + hf],
                                 Alr[mt][0], Alr[mt][1], Alr[mt][2], Alr[mt][3],
                                 Br[pg][hf * 2], Br[pg][hf * 2 + 1]);
                        }
                    }
                }
            }
            // no trailing sync: next iter's stage happens after its own sync
        }

        // epilogue: atomic-accumulate onto AR base
        int g = lane >> 2, tq = lane & 3;
        #pragma unroll
        for (int mt = 0; mt < 2; mt++) {
            #pragma unroll
            for (int nt = 0; nt < 8; nt++) {
                int row = rowbase + mg * 32 + mt * 16 + g;
                int col = ng * 64 + nt * 8 + 2 * tq;
                int b = col >> 6, o = col & 63;
                float* p0 = out + (((size_t)b * 4096 + row) * 64 + o);
                atomicAdd(p0,              c[mt][nt][0]);
                atomicAdd(p0 + 1,          c[mt][nt][1]);
                atomicAdd(p0 + 8 * 64,     c[mt][nt][2]);
                atomicAdd(p0 + 8 * 64 + 1, c[mt][nt][3]);
            }
        }
    }
}

// ---------------------------------------------------------------------------
extern "C" void kernel_launch(void* const* d_in, const int* in_sizes, int n_in,
                              void* d_out, int out_size) {
    const float* x   = (const float*)d_in[0];   // (2,4096,64)
    const float* phi = (const float*)d_in[1];   // (4096,40)
    const float* M   = (const float*)d_in[2];   // (64,64,3)
    const float* Mp  = (const float*)d_in[3];   // (40,64,64)
    const float* Mm  = (const float*)d_in[4];   // (40,64,64)
    float* out = (float*)d_out;                 // (2,4096,64)

    cudaFuncSetAttribute(k_gemm, cudaFuncAttributeMaxDynamicSharedMemorySize, SMEM_TOTAL);

    k_prep<<<(NK * L + 255) / 256, 256>>>(phi);
    k_ar<<<(2 * L * 64) / 256, 256>>>(x, M, out);
    k_z<<<dim3(64, 2, NK), 256>>>(x, Mp, Mm);
    k_gemm<<<dim3(16, 2, NK), 256, SMEM_TOTAL>>>(out);
}

// round 10
// speedup vs baseline: 4.5024x; 1.4538x over previous
#include <cuda_runtime.h>
#include <cuda_fp16.h>

#define L    4096
#define NK   40

// ---------------------------------------------------------------------------
// Global scratch (static; no allocations)
__device__ unsigned g_phiP[NK * L];     // packed fp16 hi | lo<<16 of phi[lag]
__device__ __half   g_B[(size_t)NK * 2 * 128 * L];  // [k][par][n][s] fp16
// par=0: B'[s]  = (s even ? Zp+Zm : Zp-Zm)   (feeds even-t rows)
// par=1: B''[s] = (s even ? Zp-Zm : Zp+Zm)   (feeds odd-t rows)

// ---------------------------------------------------------------------------
__device__ __forceinline__ unsigned smem_u32(const void* p) {
    unsigned a;
    asm("{ .reg .u64 t; cvta.to.shared.u64 t, %1; cvt.u32.u64 %0, t; }" : "=r"(a) : "l"(p));
    return a;
}
__device__ __forceinline__ unsigned packhf(float v) {
    __half h = __float2half_rn(v);
    float r = v - __half2float(h);
    __half l = __float2half_rn(r);
    return (unsigned)__half_as_ushort(h) | ((unsigned)__half_as_ushort(l) << 16);
}
__device__ __forceinline__ void ldsm4(unsigned& r0, unsigned& r1, unsigned& r2,
                                      unsigned& r3, unsigned addr) {
    asm volatile("ldmatrix.sync.aligned.m8n8.x4.shared.b16 {%0,%1,%2,%3}, [%4];"
                 : "=r"(r0), "=r"(r1), "=r"(r2), "=r"(r3) : "r"(addr));
}
__device__ __forceinline__ void hmma(float* c, unsigned a0, unsigned a1, unsigned a2,
                                     unsigned a3, unsigned b0, unsigned b1) {
    asm volatile(
        "mma.sync.aligned.m16n8k16.row.col.f32.f16.f16.f32 "
        "{%0,%1,%2,%3},{%4,%5,%6,%7},{%8,%9},{%0,%1,%2,%3};"
        : "+f"(c[0]), "+f"(c[1]), "+f"(c[2]), "+f"(c[3])
        : "r"(a0), "r"(a1), "r"(a2), "r"(a3), "r"(b0), "r"(b1));
}
__device__ __forceinline__ void cp16(unsigned dst, const void* src) {
    asm volatile("cp.async.ca.shared.global [%0], [%1], 16;" :: "r"(dst), "l"(src));
}

// ---------------------------------------------------------------------------
// phi prep: packed fp16 hi/lo split of phi[lag], [k][lag]
__global__ void k_prep(const float* __restrict__ phi) {
    int gid = blockIdx.x * 256 + threadIdx.x;
    if (gid >= NK * L) return;
    int k = gid >> 12, lag = gid & (L - 1);
    g_phiP[(k << 12) + lag] = packhf(phi[lag * NK + k]);
}

// ---------------------------------------------------------------------------
// AR term (initializes out)
__global__ void k_ar(const float* __restrict__ x, const float* __restrict__ M,
                     float* __restrict__ out) {
    __shared__ float sM[3 * 64 * 64];
    for (int idx = threadIdx.x; idx < 64 * 64 * 3; idx += 256) {
        int o = idx / 192, rem = idx % 192, d = rem / 3, i = rem % 3;
        sM[(i * 64 + d) * 64 + o] = M[idx];
    }
    __syncthreads();
    int gid = blockIdx.x * 256 + threadIdx.x;
    int o = gid & 63;
    int t = (gid >> 6) & (L - 1);
    int b = gid >> 18;
    float acc = 0.f;
    for (int i = 0; i < 3; i++) {
        int tt = t - i;
        if (tt < 0) break;
        const float* xr = x + (((b << 12) + tt) << 6);
        const float* mr = sM + i * 4096;
        #pragma unroll 16
        for (int d = 0; d < 64; d++) acc += xr[d] * mr[d * 64 + o];
    }
    out[gid] = acc;
}

// ---------------------------------------------------------------------------
// Z build (fp32 math), emits parity-folded fp16 B' / B'' transposed [k][par][n][s]
__global__ void k_z(const float* __restrict__ x, const float* __restrict__ Mp,
                    const float* __restrict__ Mm) {
    __shared__ float sx[64][64];
    __shared__ float sM[64][64];
    int st = blockIdx.x, b = blockIdx.y, k = blockIdx.z;
    int tid = threadIdx.x, tx = tid & 15, ty = tid >> 4;
    int sbase = st * 64;

    const float* xb = x + (((b << 12) + sbase) << 6);
    for (int i = tid; i < 4096; i += 256) sx[i >> 6][i & 63] = xb[i];
    const float* mp = Mp + (k << 12);
    for (int i = tid; i < 4096; i += 256) sM[i >> 6][i & 63] = mp[i];
    __syncthreads();

    float accP[4][4] = {};
    #pragma unroll 8
    for (int kk = 0; kk < 64; kk++) {
        float a[4];
        #pragma unroll
        for (int i = 0; i < 4; i++) a[i] = sx[ty * 4 + i][kk];
        float4 bv = *(float4*)&sM[kk][tx * 4];
        #pragma unroll
        for (int i = 0; i < 4; i++) {
            accP[i][0] += a[i] * bv.x; accP[i][1] += a[i] * bv.y;
            accP[i][2] += a[i] * bv.z; accP[i][3] += a[i] * bv.w;
        }
    }
    __syncthreads();

    const float* mm = Mm + (k << 12);
    for (int i = tid; i < 4096; i += 256) sM[i >> 6][i & 63] = mm[i];
    __syncthreads();

    float accM[4][4] = {};
    #pragma unroll 8
    for (int kk = 0; kk < 64; kk++) {
        float a[4];
        #pragma unroll
        for (int i = 0; i < 4; i++) a[i] = sx[ty * 4 + i][kk];
        float4 bv = *(float4*)&sM[kk][tx * 4];
        #pragma unroll
        for (int i = 0; i < 4; i++) {
            accM[i][0] += a[i] * bv.x; accM[i][1] += a[i] * bv.y;
            accM[i][2] += a[i] * bv.z; accM[i][3] += a[i] * bv.w;
        }
    }

    int srow = sbase + ty * 4;   // even; rows srow+i have parity i&1
    #pragma unroll
    for (int j = 0; j < 4; j++) {
        int n = (b << 6) + tx * 4 + j;
        float s0 = accP[0][j] + accM[0][j], d0 = accP[0][j] - accM[0][j];
        float s1 = accP[1][j] + accM[1][j], d1 = accP[1][j] - accM[1][j];
        float s2 = accP[2][j] + accM[2][j], d2 = accP[2][j] - accM[2][j];
        float s3 = accP[3][j] + accM[3][j], d3 = accP[3][j] - accM[3][j];
        // B'  (even-t GEMM): s even -> sum, s odd -> dif
        __half2 e01 = __floats2half2_rn(s0, d1);
        __half2 e23 = __floats2half2_rn(s2, d3);
        // B'' (odd-t GEMM):  s even -> dif, s odd -> sum
        __half2 o01 = __floats2half2_rn(d0, s1);
        __half2 o23 = __floats2half2_rn(d2, s3);
        uint2 ve = make_uint2(*(unsigned*)&e01, *(unsigned*)&e23);
        uint2 vo = make_uint2(*(unsigned*)&o01, *(unsigned*)&o23);
        *(uint2*)&g_B[((size_t)(k * 2 + 0) * 128 + n) * 4096 + srow] = ve;
        *(uint2*)&g_B[((size_t)(k * 2 + 1) * 128 + n) * 4096 + srow] = vo;
    }
}

// ---------------------------------------------------------------------------
// HMMA polyphase Toeplitz GEMM. CTA = (row-tile rt, parity par, filter k).
// Tile rows m=0..127 are t = 256*rt + 2m + par. A[m][kk] = phi[Dd + 2m - kk].
// fp16 2-product (A hi/lo, B single), cp.async double-buffered B.
#define ROWB     144
#define TILEB    (128 * ROWB)          // 18432
#define OFF_A    1536                  // 4 tiles: [buf][h/l]
#define OFF_B    (OFF_A + 4 * TILEB)   // 2 tiles: [buf]
#define SMEM_TOTAL (OFF_B + 2 * TILEB) // 112128

__global__ void __launch_bounds__(256, 2) k_gemm(float* __restrict__ out) {
    extern __shared__ char smem[];
    unsigned sbu = smem_u32(smem);
    int tid = threadIdx.x, wid = tid >> 5, lane = tid & 31;
    int rt = 15 - (int)blockIdx.x;     // big tiles first
    int par = blockIdx.y, k = blockIdx.z;
    int tbase = (rt << 8) + par;
    int mg = wid >> 1, ng = wid & 1;   // warp tile: rows [mg*32,+32), cols [ng*64,+64)

    const unsigned* phiArr = g_phiP + (k << 12);
    const char* Bsrc = (const char*)(g_B + (size_t)(k * 2 + par) * 128 * 4096);

    unsigned aLaneOff = (unsigned)((mg * 32 + (lane & 15)) * ROWB + (lane >> 4) * 16);
    unsigned bLaneOff = (unsigned)((ng * 64 + (lane & 7) + ((lane >> 4) & 1) * 8) * ROWB
                                   + ((lane >> 3) & 1) * 16);
    unsigned* win = (unsigned*)smem;   // 320 entries

    // B copy assignment: thread -> row (tid>>1), 4x16B at seg (tid&1)*64
    int crow = tid >> 1;
    int cseg = (tid & 1) * 64;
    size_t crowByte = (size_t)crow * 8192;
    unsigned cdstBase = sbu + OFF_B + crow * ROWB + cseg;

    int am = tid >> 1, ah2 = tid & 1;  // A build: row m, kk-half
    int wbase = 2 * am + 63 - ah2 * 32;

    int nch = 4 * (rt + 1);

    float c[2][8][4];
    #pragma unroll
    for (int i = 0; i < 2; i++)
        #pragma unroll
        for (int j = 0; j < 8; j++)
            #pragma unroll
            for (int q = 0; q < 4; q++) c[i][j][q] = 0.f;

    // prologue: prefetch B chunk 0 -> buf0
    {
        const char* src = Bsrc + crowByte + cseg;
        #pragma unroll
        for (int q = 0; q < 4; q++) cp16(cdstBase + q * 16, src + q * 16);
        asm volatile("cp.async.commit_group;");
    }

    for (int sbk = 0; sbk < nch; sbk++) {
        int p = sbk & 1;
        int Dd = tbase - (sbk << 6);

        // stage phi window [Dd-63, Dd+256]
        for (int w = tid; w < 320; w += 256) {
            int lag = Dd - 63 + w;
            win[w] = (lag >= 0 && lag < L) ? phiArr[lag] : 0u;
        }
        __syncthreads();

        // build A tiles (hi, lo) into Abuf[p]: A[m][kk] = win[2m - kk + 63]
        {
            char* Ah = smem + OFF_A + (p * 2 + 0) * TILEB + am * ROWB + ah2 * 64;
            char* Al = smem + OFF_A + (p * 2 + 1) * TILEB + am * ROWB + ah2 * 64;
            #pragma unroll
            for (int q = 0; q < 8; q++) {
                unsigned P0 = win[wbase - 4 * q];
                unsigned P1 = win[wbase - 4 * q - 1];
                unsigned P2 = win[wbase - 4 * q - 2];
                unsigned P3 = win[wbase - 4 * q - 3];
                uint2 h, l;
                h.x = (P0 & 0xffffu) | (P1 << 16);
                h.y = (P2 & 0xffffu) | (P3 << 16);
                l.x = (P0 >> 16) | (P1 & 0xffff0000u);
                l.y = (P2 >> 16) | (P3 & 0xffff0000u);
                *(uint2*)(Ah + q * 8) = h;
                *(uint2*)(Al + q * 8) = l;
            }
        }

        asm volatile("cp.async.wait_group 0;");   // B[p] arrived
        __syncthreads();

        // prefetch next B chunk into buf[p^1] (overlaps MMA below)
        if (sbk + 1 < nch) {
            const char* src = Bsrc + crowByte + ((size_t)(sbk + 1) << 7) + cseg;
            unsigned dst = cdstBase + (p ^ 1) * TILEB;
            #pragma unroll
            for (int q = 0; q < 4; q++) cp16(dst + q * 16, src + q * 16);
            asm volatile("cp.async.commit_group;");
        }

        // MMA phase: 4 k-steps of 16
        unsigned aH = sbu + OFF_A + (p * 2) * TILEB + aLaneOff;
        unsigned aL = aH + TILEB;
        unsigned bB = sbu + OFF_B + p * TILEB + bLaneOff;
        #pragma unroll
        for (int ks = 0; ks < 4; ks++) {
            unsigned ko = ks * 32;
            unsigned Ahr[2][4], Alr[2][4], Br[4][4];
            #pragma unroll
            for (int mt = 0; mt < 2; mt++) {
                ldsm4(Ahr[mt][0], Ahr[mt][1], Ahr[mt][2], Ahr[mt][3],
                      aH + mt * (16 * ROWB) + ko);
                ldsm4(Alr[mt][0], Alr[mt][1], Alr[mt][2], Alr[mt][3],
                      aL + mt * (16 * ROWB) + ko);
            }
            #pragma unroll
            for (int pg = 0; pg < 4; pg++)
                ldsm4(Br[pg][0], Br[pg][1], Br[pg][2], Br[pg][3],
                      bB + pg * (16 * ROWB) + ko);
            #pragma unroll
            for (int mt = 0; mt < 2; mt++) {
                #pragma unroll
                for (int pg = 0; pg < 4; pg++) {
                    #pragma unroll
                    for (int hf = 0; hf < 2; hf++) {
                        hmma(c[mt][pg * 2 + hf],
                             Ahr[mt][0], Ahr[mt][1], Ahr[mt][2], Ahr[mt][3],
                             Br[pg][hf * 2], Br[pg][hf * 2 + 1]);
                        hmma(c[mt][pg * 2 + hf],
                             Alr[mt][0], Alr[mt][1], Alr[mt][2], Alr[mt][3],
                             Br[pg][hf * 2], Br[pg][hf * 2 + 1]);
                    }
                }
            }
        }
    }

    // epilogue: t = tbase + 2*rowInTile; atomic-accumulate onto AR base
    int g = lane >> 2, tq = lane & 3;
    #pragma unroll
    for (int mt = 0; mt < 2; mt++) {
        #pragma unroll
        for (int nt = 0; nt < 8; nt++) {
            int rowIn = mg * 32 + mt * 16 + g;
            int t = tbase + 2 * rowIn;
            int col = ng * 64 + nt * 8 + 2 * tq;
            int b = col >> 6, o = col & 63;
            float* p0 = out + (((size_t)b * 4096 + t) * 64 + o);
            atomicAdd(p0,               c[mt][nt][0]);
            atomicAdd(p0 + 1,           c[mt][nt][1]);
            atomicAdd(p0 + 16 * 64,     c[mt][nt][2]);   // rowIn+8 -> t+16
            atomicAdd(p0 + 16 * 64 + 1, c[mt][nt][3]);
        }
    }
}

// ---------------------------------------------------------------------------
extern "C" void kernel_launch(void* const* d_in, const int* in_sizes, int n_in,
                              void* d_out, int out_size) {
    const float* x   = (const float*)d_in[0];   // (2,4096,64)
    const float* phi = (const float*)d_in[1];   // (4096,40)
    const float* M   = (const float*)d_in[2];   // (64,64,3)
    const float* Mp  = (const float*)d_in[3];   // (40,64,64)
    const float* Mm  = (const float*)d_in[4];   // (40,64,64)
    float* out = (float*)d_out;                 // (2,4096,64)

    cudaFuncSetAttribute(k_gemm, cudaFuncAttributeMaxDynamicSharedMemorySize, SMEM_TOTAL);

    k_prep<<<(NK * L + 255) / 256, 256>>>(phi);
    k_ar<<<(2 * L * 64) / 256, 256>>>(x, M, out);
    k_z<<<dim3(64, 2, NK), 256>>>(x, Mp, Mm);
    k_gemm<<<dim3(16, 2, NK), 256, SMEM_TOTAL>>>(out);
}

// round 12
// speedup vs baseline: 6.6821x; 1.4841x over previous
#include <cuda_runtime.h>
#include <cuda_fp16.h>

#define L    4096
#define NK   40

// ---------------------------------------------------------------------------
// Global scratch (static; no allocations)
__device__ __half g_phi[NK * L];                    // fp16 phi[lag], [k][lag]
__device__ __half g_B[(size_t)NK * 2 * 128 * L];    // [k][par][n][s] fp16
// par=0: B'[s]  = (s even ? Zp+Zm : Zp-Zm)   (feeds even-t rows)
// par=1: B''[s] = (s even ? Zp-Zm : Zp+Zm)   (feeds odd-t rows)

// ---------------------------------------------------------------------------
__device__ __forceinline__ unsigned smem_u32(const void* p) {
    unsigned a;
    asm("{ .reg .u64 t; cvta.to.shared.u64 t, %1; cvt.u32.u64 %0, t; }" : "=r"(a) : "l"(p));
    return a;
}
__device__ __forceinline__ void ldsm4(unsigned& r0, unsigned& r1, unsigned& r2,
                                      unsigned& r3, unsigned addr) {
    asm volatile("ldmatrix.sync.aligned.m8n8.x4.shared.b16 {%0,%1,%2,%3}, [%4];"
                 : "=r"(r0), "=r"(r1), "=r"(r2), "=r"(r3) : "r"(addr));
}
__device__ __forceinline__ void hmma(float* c, unsigned a0, unsigned a1, unsigned a2,
                                     unsigned a3, unsigned b0, unsigned b1) {
    asm volatile(
        "mma.sync.aligned.m16n8k16.row.col.f32.f16.f16.f32 "
        "{%0,%1,%2,%3},{%4,%5,%6,%7},{%8,%9},{%0,%1,%2,%3};"
        : "+f"(c[0]), "+f"(c[1]), "+f"(c[2]), "+f"(c[3])
        : "r"(a0), "r"(a1), "r"(a2), "r"(a3), "r"(b0), "r"(b1));
}
__device__ __forceinline__ void cp16(unsigned dst, const void* src) {
    asm volatile("cp.async.ca.shared.global [%0], [%1], 16;" :: "r"(dst), "l"(src));
}

// ---------------------------------------------------------------------------
// phi prep: single fp16
__global__ void k_prep(const float* __restrict__ phi) {
    int gid = blockIdx.x * 256 + threadIdx.x;
    if (gid >= NK * L) return;
    int k = gid >> 12, lag = gid & (L - 1);
    g_phi[(k << 12) + lag] = __float2half_rn(phi[lag * NK + k]);
}

// ---------------------------------------------------------------------------
// AR term (initializes out)
__global__ void k_ar(const float* __restrict__ x, const float* __restrict__ M,
                     float* __restrict__ out) {
    __shared__ float sM[3 * 64 * 64];
    for (int idx = threadIdx.x; idx < 64 * 64 * 3; idx += 256) {
        int o = idx / 192, rem = idx % 192, d = rem / 3, i = rem % 3;
        sM[(i * 64 + d) * 64 + o] = M[idx];
    }
    __syncthreads();
    int gid = blockIdx.x * 256 + threadIdx.x;
    int o = gid & 63;
    int t = (gid >> 6) & (L - 1);
    int b = gid >> 18;
    float acc = 0.f;
    for (int i = 0; i < 3; i++) {
        int tt = t - i;
        if (tt < 0) break;
        const float* xr = x + (((b << 12) + tt) << 6);
        const float* mr = sM + i * 4096;
        #pragma unroll 16
        for (int d = 0; d < 64; d++) acc += xr[d] * mr[d * 64 + o];
    }
    out[gid] = acc;
}

// ---------------------------------------------------------------------------
// HMMA Z build. CTA = (s-tile of 128, batch b, filter k).
// A[128,64] = [Mp^T ; Mm^T] fp16 (single), B = x tile fp16 hi/lo (2 products).
// C[m,s]: rows 0-63 = Zp^T, 64-127 = Zm^T. Epilogue parity-folds into g_B.
#define ZROWB   144
#define ZOFF_A  0
#define ZOFF_BH (ZOFF_A + 128 * ZROWB)
#define ZOFF_BL (ZOFF_BH + 128 * ZROWB)
#define ZOFF_ST (ZOFF_BL + 128 * ZROWB)          // 64 x 132 fp32 stage
#define ZSMEM   (ZOFF_ST + 64 * 132 * 4)         // 89088

__global__ void __launch_bounds__(256) k_z(const float* __restrict__ x,
                                           const float* __restrict__ Mp,
                                           const float* __restrict__ Mm) {
    extern __shared__ char smem[];
    unsigned sbu = smem_u32(smem);
    int tid = threadIdx.x, wid = tid >> 5, lane = tid & 31;
    int stile = blockIdx.x, b = blockIdx.y, k = blockIdx.z;
    int mg = wid >> 2, ng = wid & 3;   // warp: m-half (Zp/Zm), s-group of 32

    // load A: Mp -> rows 0-63, Mm -> rows 64-127 (A[o][d] = M[d][o])
    const float* mp = Mp + (k << 12);
    const float* mm = Mm + (k << 12);
    for (int i = tid; i < 4096; i += 256) {
        int d = i >> 6, o = i & 63;
        *(__half*)(smem + ZOFF_A + o * ZROWB + d * 2) = __float2half_rn(mp[i]);
        *(__half*)(smem + ZOFF_A + (o + 64) * ZROWB + d * 2) = __float2half_rn(mm[i]);
    }
    // load x tile [128 s][64 d], split hi/lo fp16
    const float* xb = x + (((size_t)(b << 12) + (stile << 7)) << 6);
    for (int i = tid; i < 2048; i += 256) {
        int row = i >> 4, c4 = (i & 15) * 4;
        float4 v = ((const float4*)xb)[i];
        __half h0 = __float2half_rn(v.x), h1 = __float2half_rn(v.y);
        __half h2 = __float2half_rn(v.z), h3 = __float2half_rn(v.w);
        __half l0 = __float2half_rn(v.x - __half2float(h0));
        __half l1 = __float2half_rn(v.y - __half2float(h1));
        __half l2 = __float2half_rn(v.z - __half2float(h2));
        __half l3 = __float2half_rn(v.w - __half2float(h3));
        __half2 hh0 = __halves2half2(h0, h1), hh1 = __halves2half2(h2, h3);
        __half2 ll0 = __halves2half2(l0, l1), ll1 = __halves2half2(l2, l3);
        *(uint2*)(smem + ZOFF_BH + row * ZROWB + c4 * 2) =
            make_uint2(*(unsigned*)&hh0, *(unsigned*)&hh1);
        *(uint2*)(smem + ZOFF_BL + row * ZROWB + c4 * 2) =
            make_uint2(*(unsigned*)&ll0, *(unsigned*)&ll1);
    }
    __syncthreads();

    unsigned aOff = sbu + ZOFF_A + (unsigned)((mg * 64 + (lane & 15)) * ZROWB + (lane >> 4) * 16);
    unsigned bOff = (unsigned)((ng * 32 + (lane & 7) + ((lane >> 4) & 1) * 8) * ZROWB
                               + ((lane >> 3) & 1) * 16);
    unsigned bH = sbu + ZOFF_BH + bOff, bL = sbu + ZOFF_BL + bOff;

    float c[4][4][4];
    #pragma unroll
    for (int i = 0; i < 4; i++)
        #pragma unroll
        for (int j = 0; j < 4; j++)
            #pragma unroll
            for (int q = 0; q < 4; q++) c[i][j][q] = 0.f;

    #pragma unroll
    for (int ks = 0; ks < 4; ks++) {
        unsigned ko = ks * 32;
        unsigned Ar[4][4], Bh[2][4], Bl[2][4];
        #pragma unroll
        for (int mt = 0; mt < 4; mt++)
            ldsm4(Ar[mt][0], Ar[mt][1], Ar[mt][2], Ar[mt][3],
                  aOff + mt * (16 * ZROWB) + ko);
        #pragma unroll
        for (int pg = 0; pg < 2; pg++) {
            ldsm4(Bh[pg][0], Bh[pg][1], Bh[pg][2], Bh[pg][3],
                  bH + pg * (16 * ZROWB) + ko);
            ldsm4(Bl[pg][0], Bl[pg][1], Bl[pg][2], Bl[pg][3],
                  bL + pg * (16 * ZROWB) + ko);
        }
        #pragma unroll
        for (int mt = 0; mt < 4; mt++) {
            #pragma unroll
            for (int pg = 0; pg < 2; pg++) {
                #pragma unroll
                for (int hf = 0; hf < 2; hf++) {
                    int nt = pg * 2 + hf;
                    hmma(c[mt][nt], Ar[mt][0], Ar[mt][1], Ar[mt][2], Ar[mt][3],
                         Bh[pg][hf * 2], Bh[pg][hf * 2 + 1]);
                    hmma(c[mt][nt], Ar[mt][0], Ar[mt][1], Ar[mt][2], Ar[mt][3],
                         Bl[pg][hf * 2], Bl[pg][hf * 2 + 1]);
                }
            }
        }
    }
    __syncthreads();

    float* stg = (float*)(smem + ZOFF_ST);
    int g = lane >> 2, q = lane & 3;
    if (mg == 1) {   // stage Zm
        #pragma unroll
        for (int mt = 0; mt < 4; mt++) {
            #pragma unroll
            for (int nt = 0; nt < 4; nt++) {
                int o = mt * 16 + g;
                int sc = ng * 32 + nt * 8 + 2 * q;
                stg[o * 132 + sc]       = c[mt][nt][0];
                stg[o * 132 + sc + 1]   = c[mt][nt][1];
                stg[(o + 8) * 132 + sc]     = c[mt][nt][2];
                stg[(o + 8) * 132 + sc + 1] = c[mt][nt][3];
            }
        }
    }
    __syncthreads();
    if (mg == 0) {   // fold + write both parities
        #pragma unroll
        for (int mt = 0; mt < 4; mt++) {
            #pragma unroll
            for (int nt = 0; nt < 4; nt++) {
                int sc = ng * 32 + nt * 8 + 2 * q;       // even local s
                #pragma unroll
                for (int hh = 0; hh < 2; hh++) {
                    int o = mt * 16 + g + hh * 8;
                    float zp0 = c[mt][nt][hh * 2], zp1 = c[mt][nt][hh * 2 + 1];
                    float zm0 = stg[o * 132 + sc], zm1 = stg[o * 132 + sc + 1];
                    float s0 = zp0 + zm0, d0 = zp0 - zm0;
                    float s1 = zp1 + zm1, d1 = zp1 - zm1;
                    __half2 ev = __floats2half2_rn(s0, d1);
                    __half2 od = __floats2half2_rn(d0, s1);
                    int n = (b << 6) + o;
                    size_t sg = (size_t)(stile << 7) + sc;
                    *(unsigned*)&g_B[((size_t)(k * 2 + 0) * 128 + n) * 4096 + sg] =
                        *(unsigned*)&ev;
                    *(unsigned*)&g_B[((size_t)(k * 2 + 1) * 128 + n) * 4096 + sg] =
                        *(unsigned*)&od;
                }
            }
        }
    }
}

// ---------------------------------------------------------------------------
// HMMA polyphase Toeplitz GEMM. CTA = (row-tile rt, parity par, filter k).
// Tile rows m=0..127 are t = 256*rt + 2m + par. A[m][kk] = phi[Dd + 2m - kk].
// Single fp16 product (A fp16, B fp16), cp.async double-buffered B.
#define ROWB     144
#define TILEB    (128 * ROWB)          // 18432
#define OFF_A    768                   // 2 tiles: [buf]
#define OFF_B    (OFF_A + 2 * TILEB)   // 2 tiles: [buf]
#define SMEM_TOTAL (OFF_B + 2 * TILEB) // 74496

__global__ void __launch_bounds__(256, 2) k_gemm(float* __restrict__ out) {
    extern __shared__ char smem[];
    unsigned sbu = smem_u32(smem);
    int tid = threadIdx.x, wid = tid >> 5, lane = tid & 31;
    int rt = 15 - (int)blockIdx.x;     // big tiles first
    int par = blockIdx.y, k = blockIdx.z;
    int tbase = (rt << 8) + par;
    int mg = wid >> 1, ng = wid & 1;   // warp tile: rows [mg*32,+32), cols [ng*64,+64)

    const unsigned short* phiArr = (const unsigned short*)(g_phi + (k << 12));
    const char* Bsrc = (const char*)(g_B + (size_t)(k * 2 + par) * 128 * 4096);

    unsigned aLaneOff = (unsigned)((mg * 32 + (lane & 15)) * ROWB + (lane >> 4) * 16);
    unsigned bLaneOff = (unsigned)((ng * 64 + (lane & 7) + ((lane >> 4) & 1) * 8) * ROWB
                                   + ((lane >> 3) & 1) * 16);
    unsigned short* win = (unsigned short*)smem;   // 320 entries

    // B copy assignment: thread -> row (tid>>1), 4x16B at seg (tid&1)*64
    int crow = tid >> 1;
    int cseg = (tid & 1) * 64;
    size_t crowByte = (size_t)crow * 8192;
    unsigned cdstBase = sbu + OFF_B + crow * ROWB + cseg;

    int am = tid >> 1, ah2 = tid & 1;  // A build: row m, kk-half
    int wbase = 2 * am + 63 - ah2 * 32;

    int nch = 4 * (rt + 1);

    float c[2][8][4];
    #pragma unroll
    for (int i = 0; i < 2; i++)
        #pragma unroll
        for (int j = 0; j < 8; j++)
            #pragma unroll
            for (int q = 0; q < 4; q++) c[i][j][q] = 0.f;

    // prologue: prefetch B chunk 0 -> buf0
    {
        const char* src = Bsrc + crowByte + cseg;
        #pragma unroll
        for (int q = 0; q < 4; q++) cp16(cdstBase + q * 16, src + q * 16);
        asm volatile("cp.async.commit_group;");
    }

    for (int sbk = 0; sbk < nch; sbk++) {
        int p = sbk & 1;
        int Dd = tbase - (sbk << 6);

        // stage phi window [Dd-63, Dd+256] (320 fp16)
        for (int w = tid; w < 320; w += 256) {
            int lag = Dd - 63 + w;
            win[w] = (lag >= 0 && lag < L) ? phiArr[lag] : (unsigned short)0;
        }
        __syncthreads();

        // build A tile into Abuf[p]: A[m][kk] = win[2m - kk + 63]
        {
            char* Ah = smem + OFF_A + p * TILEB + am * ROWB + ah2 * 64;
            #pragma unroll
            for (int q = 0; q < 8; q++) {
                unsigned w0 = win[wbase - 4 * q];
                unsigned w1 = win[wbase - 4 * q - 1];
                unsigned w2 = win[wbase - 4 * q - 2];
                unsigned w3 = win[wbase - 4 * q - 3];
                uint2 h;
                h.x = w0 | (w1 << 16);
                h.y = w2 | (w3 << 16);
                *(uint2*)(Ah + q * 8) = h;
            }
        }

        asm volatile("cp.async.wait_group 0;");   // B[p] arrived
        __syncthreads();

        // prefetch next B chunk into buf[p^1] (overlaps MMA below)
        if (sbk + 1 < nch) {
            const char* src = Bsrc + crowByte + ((size_t)(sbk + 1) << 7) + cseg;
            unsigned dst = cdstBase + (p ^ 1) * TILEB;
            #pragma unroll
            for (int q = 0; q < 4; q++) cp16(dst + q * 16, src + q * 16);
            asm volatile("cp.async.commit_group;");
        }

        // MMA phase: 4 k-steps of 16
        unsigned aH = sbu + OFF_A + p * TILEB + aLaneOff;
        unsigned bB = sbu + OFF_B + p * TILEB + bLaneOff;
        #pragma unroll
        for (int ks = 0; ks < 4; ks++) {
            unsigned ko = ks * 32;
            unsigned Ahr[2][4], Br[4][4];
            #pragma unroll
            for (int mt = 0; mt < 2; mt++)
                ldsm4(Ahr[mt][0], Ahr[mt][1], Ahr[mt][2], Ahr[mt][3],
                      aH + mt * (16 * ROWB) + ko);
            #pragma unroll
            for (int pg = 0; pg < 4; pg++)
                ldsm4(Br[pg][0], Br[pg][1], Br[pg][2], Br[pg][3],
                      bB + pg * (16 * ROWB) + ko);
            #pragma unroll
            for (int mt = 0; mt < 2; mt++) {
                #pragma unroll
                for (int pg = 0; pg < 4; pg++) {
                    #pragma unroll
                    for (int hf = 0; hf < 2; hf++) {
                        hmma(c[mt][pg * 2 + hf],
                             Ahr[mt][0], Ahr[mt][1], Ahr[mt][2], Ahr[mt][3],
                             Br[pg][hf * 2], Br[pg][hf * 2 + 1]);
                    }
                }
            }
        }
    }

    // epilogue: t = tbase + 2*rowInTile; atomic-accumulate onto AR base
    int g = lane >> 2, tq = lane & 3;
    #pragma unroll
    for (int mt = 0; mt < 2; mt++) {
        #pragma unroll
        for (int nt = 0; nt < 8; nt++) {
            int rowIn = mg * 32 + mt * 16 + g;
            int t = tbase + 2 * rowIn;
            int col = ng * 64 + nt * 8 + 2 * tq;
            int b = col >> 6, o = col & 63;
            float* p0 = out + (((size_t)b * 4096 + t) * 64 + o);
            atomicAdd(p0,               c[mt][nt][0]);
            atomicAdd(p0 + 1,           c[mt][nt][1]);
            atomicAdd(p0 + 16 * 64,     c[mt][nt][2]);   // rowIn+8 -> t+16
            atomicAdd(p0 + 16 * 64 + 1, c[mt][nt][3]);
        }
    }
}

// ---------------------------------------------------------------------------
extern "C" void kernel_launch(void* const* d_in, const int* in_sizes, int n_in,
                              void* d_out, int out_size) {
    const float* x   = (const float*)d_in[0];   // (2,4096,64)
    const float* phi = (const float*)d_in[1];   // (4096,40)
    const float* M   = (const float*)d_in[2];   // (64,64,3)
    const float* Mp  = (const float*)d_in[3];   // (40,64,64)
    const float* Mm  = (const float*)d_in[4];   // (40,64,64)
    float* out = (float*)d_out;                 // (2,4096,64)

    cudaFuncSetAttribute(k_gemm, cudaFuncAttributeMaxDynamicSharedMemorySize, SMEM_TOTAL);
    cudaFuncSetAttribute(k_z, cudaFuncAttributeMaxDynamicSharedMemorySize, ZSMEM);

    k_prep<<<(NK * L + 255) / 256, 256>>>(phi);
    k_ar<<<(2 * L * 64) / 256, 256>>>(x, M, out);
    k_z<<<dim3(32, 2, NK), 256, ZSMEM>>>(x, Mp, Mm);
    k_gemm<<<dim3(16, 2, NK), 256, SMEM_TOTAL>>>(out);
}

// round 13
// speedup vs baseline: 7.4495x; 1.1148x over previous
#include <cuda_runtime.h>
#include <cuda_fp16.h>

#define L    4096
#define NK   40

// ---------------------------------------------------------------------------
// Global scratch (static; no allocations)
__device__ __half g_phi[NK * L];                    // fp16 phi[lag], [k][lag]
__device__ __half g_Mh[NK * 128 * 64];              // [k][o-stack][d]: rows 0-63 Mp^T, 64-127 Mm^T
__device__ __half g_xh[2 * L * 64];                 // fp16 hi of x
__device__ __half g_xl[2 * L * 64];                 // fp16 lo of x
__device__ __half g_B[(size_t)NK * 2 * 128 * L];    // [k][par][n][s] fp16
// par=0: B'[s]  = (s even ? Zp+Zm : Zp-Zm)   (feeds even-t rows)
// par=1: B''[s] = (s even ? Zp-Zm : Zp+Zm)   (feeds odd-t rows)

// ---------------------------------------------------------------------------
__device__ __forceinline__ unsigned smem_u32(const void* p) {
    unsigned a;
    asm("{ .reg .u64 t; cvta.to.shared.u64 t, %1; cvt.u32.u64 %0, t; }" : "=r"(a) : "l"(p));
    return a;
}
__device__ __forceinline__ void ldsm4(unsigned& r0, unsigned& r1, unsigned& r2,
                                      unsigned& r3, unsigned addr) {
    asm volatile("ldmatrix.sync.aligned.m8n8.x4.shared.b16 {%0,%1,%2,%3}, [%4];"
                 : "=r"(r0), "=r"(r1), "=r"(r2), "=r"(r3) : "r"(addr));
}
__device__ __forceinline__ void hmma(float* c, unsigned a0, unsigned a1, unsigned a2,
                                     unsigned a3, unsigned b0, unsigned b1) {
    asm volatile(
        "mma.sync.aligned.m16n8k16.row.col.f32.f16.f16.f32 "
        "{%0,%1,%2,%3},{%4,%5,%6,%7},{%8,%9},{%0,%1,%2,%3};"
        : "+f"(c[0]), "+f"(c[1]), "+f"(c[2]), "+f"(c[3])
        : "r"(a0), "r"(a1), "r"(a2), "r"(a3), "r"(b0), "r"(b1));
}
__device__ __forceinline__ void cp16(unsigned dst, const void* src) {
    asm volatile("cp.async.ca.shared.global [%0], [%1], 16;" :: "r"(dst), "l"(src));
}

// ---------------------------------------------------------------------------
// prep: phi fp16
__global__ void k_prep(const float* __restrict__ phi) {
    int gid = blockIdx.x * 256 + threadIdx.x;
    if (gid >= NK * L) return;
    int k = gid >> 12, lag = gid & (L - 1);
    g_phi[(k << 12) + lag] = __float2half_rn(phi[lag * NK + k]);
}
// prep: M transposed+stacked fp16  (g_Mh[k][o][d]=Mp[k][d][o]; [k][64+o][d]=Mm)
__global__ void k_prep_m(const float* __restrict__ Mp, const float* __restrict__ Mm) {
    int gid = blockIdx.x * 256 + threadIdx.x;
    if (gid >= NK * 64 * 64) return;
    int k = gid >> 12, rem = gid & 4095, d = rem >> 6, o = rem & 63;
    g_Mh[((size_t)k * 128 + o) * 64 + d]      = __float2half_rn(Mp[gid]);
    g_Mh[((size_t)k * 128 + 64 + o) * 64 + d] = __float2half_rn(Mm[gid]);
}
// prep: x hi/lo fp16 split
__global__ void k_prep_x(const float* __restrict__ x) {
    int gid = blockIdx.x * 256 + threadIdx.x;
    if (gid >= 2 * L * 64) return;
    float v = x[gid];
    __half h = __float2half_rn(v);
    g_xh[gid] = h;
    g_xl[gid] = __float2half_rn(v - __half2float(h));
}

// ---------------------------------------------------------------------------
// AR term (initializes out)
__global__ void k_ar(const float* __restrict__ x, const float* __restrict__ M,
                     float* __restrict__ out) {
    __shared__ float sM[3 * 64 * 64];
    for (int idx = threadIdx.x; idx < 64 * 64 * 3; idx += 256) {
        int o = idx / 192, rem = idx % 192, d = rem / 3, i = rem % 3;
        sM[(i * 64 + d) * 64 + o] = M[idx];
    }
    __syncthreads();
    int gid = blockIdx.x * 256 + threadIdx.x;
    int o = gid & 63;
    int t = (gid >> 6) & (L - 1);
    int b = gid >> 18;
    float acc = 0.f;
    for (int i = 0; i < 3; i++) {
        int tt = t - i;
        if (tt < 0) break;
        const float* xr = x + (((b << 12) + tt) << 6);
        const float* mr = sM + i * 4096;
        #pragma unroll 16
        for (int d = 0; d < 64; d++) acc += xr[d] * mr[d * 64 + o];
    }
    out[gid] = acc;
}

// ---------------------------------------------------------------------------
// HMMA Z build. CTA = (s-tile of 128, batch b, filter k). All operands
// pre-converted fp16 in global; cp.async into padded smem, MMA, parity-fold.
#define ZROWB   144
#define ZOFF_A  0
#define ZOFF_BH (128 * ZROWB)
#define ZOFF_BL (2 * 128 * ZROWB)
#define ZOFF_ST (3 * 128 * ZROWB)                // 64 x 132 fp32 stage
#define ZSMEM   (ZOFF_ST + 64 * 132 * 4)         // 89088

__global__ void __launch_bounds__(256) k_z() {
    extern __shared__ char smem[];
    unsigned sbu = smem_u32(smem);
    int tid = threadIdx.x, wid = tid >> 5, lane = tid & 31;
    int stile = blockIdx.x, b = blockIdx.y, k = blockIdx.z;
    int mg = wid >> 2, ng = wid & 3;   // warp: m-half (Zp/Zm), s-group of 32

    // cp.async: A (M stack), Bh, Bl (x split) — 128 rows x 128B each
    const char* srcA = (const char*)(g_Mh + (size_t)k * 8192);
    const char* srcH = (const char*)(g_xh + (((size_t)(b << 12) + (stile << 7)) << 6));
    const char* srcL = (const char*)(g_xl + (((size_t)(b << 12) + (stile << 7)) << 6));
    for (int i = tid; i < 1024; i += 256) {
        int row = i >> 3, seg = (i & 7) * 16;
        cp16(sbu + ZOFF_A + row * ZROWB + seg, srcA + row * 128 + seg);
        cp16(sbu + ZOFF_BH + row * ZROWB + seg, srcH + row * 128 + seg);
        cp16(sbu + ZOFF_BL + row * ZROWB + seg, srcL + row * 128 + seg);
    }
    asm volatile("cp.async.commit_group;");
    asm volatile("cp.async.wait_group 0;");
    __syncthreads();

    unsigned aOff = sbu + ZOFF_A + (unsigned)((mg * 64 + (lane & 15)) * ZROWB + (lane >> 4) * 16);
    unsigned bOff = (unsigned)((ng * 32 + (lane & 7) + ((lane >> 4) & 1) * 8) * ZROWB
                               + ((lane >> 3) & 1) * 16);
    unsigned bH = sbu + ZOFF_BH + bOff, bL = sbu + ZOFF_BL + bOff;

    float c[4][4][4];
    #pragma unroll
    for (int i = 0; i < 4; i++)
        #pragma unroll
        for (int j = 0; j < 4; j++)
            #pragma unroll
            for (int q = 0; q < 4; q++) c[i][j][q] = 0.f;

    #pragma unroll
    for (int ks = 0; ks < 4; ks++) {
        unsigned ko = ks * 32;
        unsigned Ar[4][4], Bh2[2][4], Bl2[2][4];
        #pragma unroll
        for (int mt = 0; mt < 4; mt++)
            ldsm4(Ar[mt][0], Ar[mt][1], Ar[mt][2], Ar[mt][3],
                  aOff + mt * (16 * ZROWB) + ko);
        #pragma unroll
        for (int pg = 0; pg < 2; pg++) {
            ldsm4(Bh2[pg][0], Bh2[pg][1], Bh2[pg][2], Bh2[pg][3],
                  bH + pg * (16 * ZROWB) + ko);
            ldsm4(Bl2[pg][0], Bl2[pg][1], Bl2[pg][2], Bl2[pg][3],
                  bL + pg * (16 * ZROWB) + ko);
        }
        #pragma unroll
        for (int mt = 0; mt < 4; mt++) {
            #pragma unroll
            for (int pg = 0; pg < 2; pg++) {
                #pragma unroll
                for (int hf = 0; hf < 2; hf++) {
                    int nt = pg * 2 + hf;
                    hmma(c[mt][nt], Ar[mt][0], Ar[mt][1], Ar[mt][2], Ar[mt][3],
                         Bh2[pg][hf * 2], Bh2[pg][hf * 2 + 1]);
                    hmma(c[mt][nt], Ar[mt][0], Ar[mt][1], Ar[mt][2], Ar[mt][3],
                         Bl2[pg][hf * 2], Bl2[pg][hf * 2 + 1]);
                }
            }
        }
    }
    __syncthreads();

    float* stg = (float*)(smem + ZOFF_ST);
    int g = lane >> 2, q = lane & 3;
    if (mg == 1) {   // stage Zm
        #pragma unroll
        for (int mt = 0; mt < 4; mt++) {
            #pragma unroll
            for (int nt = 0; nt < 4; nt++) {
                int o = mt * 16 + g;
                int sc = ng * 32 + nt * 8 + 2 * q;
                stg[o * 132 + sc]           = c[mt][nt][0];
                stg[o * 132 + sc + 1]       = c[mt][nt][1];
                stg[(o + 8) * 132 + sc]     = c[mt][nt][2];
                stg[(o + 8) * 132 + sc + 1] = c[mt][nt][3];
            }
        }
    }
    __syncthreads();
    if (mg == 0) {   // fold + write both parities
        #pragma unroll
        for (int mt = 0; mt < 4; mt++) {
            #pragma unroll
            for (int nt = 0; nt < 4; nt++) {
                int sc = ng * 32 + nt * 8 + 2 * q;       // even local s
                #pragma unroll
                for (int hh = 0; hh < 2; hh++) {
                    int o = mt * 16 + g + hh * 8;
                    float zp0 = c[mt][nt][hh * 2], zp1 = c[mt][nt][hh * 2 + 1];
                    float zm0 = stg[o * 132 + sc], zm1 = stg[o * 132 + sc + 1];
                    float s0 = zp0 + zm0, d0 = zp0 - zm0;
                    float s1 = zp1 + zm1, d1 = zp1 - zm1;
                    __half2 ev = __floats2half2_rn(s0, d1);
                    __half2 od = __floats2half2_rn(d0, s1);
                    int n = (b << 6) + o;
                    size_t sg = (size_t)(stile << 7) + sc;
                    *(unsigned*)&g_B[((size_t)(k * 2 + 0) * 128 + n) * 4096 + sg] =
                        *(unsigned*)&ev;
                    *(unsigned*)&g_B[((size_t)(k * 2 + 1) * 128 + n) * 4096 + sg] =
                        *(unsigned*)&od;
                }
            }
        }
    }
}

// ---------------------------------------------------------------------------
// HMMA polyphase Toeplitz GEMM. CTA = (row-tile rt, parity par, filter k).
// Block 128 (4 warps, 2x2), warp tile 64x64. A fragments loaded DIRECTLY from
// a reversed phi window in smem (one LDS.32 per fragment register); no A tile.
// B double-buffered via cp.async.
#define ROWB     144
#define TILEB    (128 * ROWB)          // 18432
#define GOFF_B   1536                  // after 2x640B reversed windows

__global__ void __launch_bounds__(128) k_gemm(float* __restrict__ out) {
    __shared__ char smem[GOFF_B + 2 * TILEB];
    unsigned sbu = smem_u32(smem);
    int tid = threadIdx.x, wid = tid >> 5, lane = tid & 31;
    int rt = 15 - (int)blockIdx.x;     // big tiles first
    int par = blockIdx.y, k = blockIdx.z;
    int tbase = (rt << 8) + par;
    int mg = wid >> 1, ng = wid & 1;   // warp tile: rows [mg*64,+64), cols [ng*64,+64)
    int g = lane >> 2, q = lane & 3;

    const unsigned short* phiArr = (const unsigned short*)(g_phi + (k << 12));
    const char* Bsrc = (const char*)(g_B + (size_t)(k * 2 + par) * 128 * 4096);

    // byte offset into reversed window for (mt=0, r=0, ks=0) fragment pair
    int iBase2 = 508 - 4 * (mg * 64 + g) + 4 * q;

    unsigned bLaneOff = (unsigned)((ng * 64 + (lane & 7) + ((lane >> 4) & 1) * 8) * ROWB
                                   + ((lane >> 3) & 1) * 16);

    // B copy: thread -> row tid, 8x16B
    const char* crowSrc = Bsrc + (size_t)tid * 8192;
    unsigned cdstBase = sbu + GOFF_B + tid * ROWB;

    int nch = 4 * (rt + 1);

    float c[4][8][4];
    #pragma unroll
    for (int i = 0; i < 4; i++)
        #pragma unroll
        for (int j = 0; j < 8; j++)
            #pragma unroll
            for (int qq = 0; qq < 4; qq++) c[i][j][qq] = 0.f;

    // prologue: prefetch B chunk 0 -> buf0
    #pragma unroll
    for (int s = 0; s < 8; s++) cp16(cdstBase + s * 16, crowSrc + s * 16);
    asm volatile("cp.async.commit_group;");

    for (int sbk = 0; sbk < nch; sbk++) {
        int p = sbk & 1;
        int Dd = tbase - (sbk << 6);

        // stage REVERSED phi window: winR[w] = phi[Dd+254-w], w in [0,318)
        unsigned short* win = (unsigned short*)(smem + p * 640);
        for (int w = tid; w < 318; w += 128) {
            int lag = Dd + 254 - w;
            win[w] = (lag >= 0 && lag < L) ? phiArr[lag] : (unsigned short)0;
        }
        __syncthreads();

        asm volatile("cp.async.wait_group 0;");   // B[p] arrived
        __syncthreads();

        // prefetch next B chunk into buf[p^1] (overlaps MMA below)
        if (sbk + 1 < nch) {
            const char* src = crowSrc + ((size_t)(sbk + 1) << 7);
            unsigned dst = cdstBase + (p ^ 1) * TILEB;
            #pragma unroll
            for (int s = 0; s < 8; s++) cp16(dst + s * 16, src + s * 16);
            asm volatile("cp.async.commit_group;");
        }

        // MMA phase: 4 k-steps of 16
        const char* wp0 = smem + p * 640 + iBase2;
        unsigned bB = sbu + GOFF_B + p * TILEB + bLaneOff;
        #pragma unroll
        for (int ks = 0; ks < 4; ks++) {
            const char* wp = wp0 + ks * 32;
            unsigned a[4][4];
            #pragma unroll
            for (int mt = 0; mt < 4; mt++) {
                a[mt][0] = *(const unsigned*)(wp - 64 * mt);
                a[mt][1] = *(const unsigned*)(wp - 64 * mt - 32);
                a[mt][2] = *(const unsigned*)(wp - 64 * mt + 16);
                a[mt][3] = *(const unsigned*)(wp - 64 * mt - 16);
            }
            unsigned Br[4][4];
            #pragma unroll
            for (int pg = 0; pg < 4; pg++)
                ldsm4(Br[pg][0], Br[pg][1], Br[pg][2], Br[pg][3],
                      bB + pg * (16 * ROWB) + ks * 32);
            #pragma unroll
            for (int mt = 0; mt < 4; mt++) {
                #pragma unroll
                for (int pg = 0; pg < 4; pg++) {
                    #pragma unroll
                    for (int hf = 0; hf < 2; hf++) {
                        hmma(c[mt][pg * 2 + hf],
                             a[mt][0], a[mt][1], a[mt][2], a[mt][3],
                             Br[pg][hf * 2], Br[pg][hf * 2 + 1]);
                    }
                }
            }
        }
    }

    // epilogue: t = tbase + 2*rowInTile; atomic-accumulate onto AR base
    #pragma unroll
    for (int mt = 0; mt < 4; mt++) {
        #pragma unroll
        for (int nt = 0; nt < 8; nt++) {
            int rowIn = mg * 64 + mt * 16 + g;
            int t = tbase + 2 * rowIn;
            int col = ng * 64 + nt * 8 + 2 * q;
            int b = col >> 6, o = col & 63;
            float* p0 = out + (((size_t)b * 4096 + t) * 64 + o);
            atomicAdd(p0,               c[mt][nt][0]);
            atomicAdd(p0 + 1,           c[mt][nt][1]);
            atomicAdd(p0 + 16 * 64,     c[mt][nt][2]);   // rowIn+8 -> t+16
            atomicAdd(p0 + 16 * 64 + 1, c[mt][nt][3]);
        }
    }
}

// ---------------------------------------------------------------------------
extern "C" void kernel_launch(void* const* d_in, const int* in_sizes, int n_in,
                              void* d_out, int out_size) {
    const float* x   = (const float*)d_in[0];   // (2,4096,64)
    const float* phi = (const float*)d_in[1];   // (4096,40)
    const float* M   = (const float*)d_in[2];   // (64,64,3)
    const float* Mp  = (const float*)d_in[3];   // (40,64,64)
    const float* Mm  = (const float*)d_in[4];   // (40,64,64)
    float* out = (float*)d_out;                 // (2,4096,64)

    cudaFuncSetAttribute(k_z, cudaFuncAttributeMaxDynamicSharedMemorySize, ZSMEM);

    k_prep<<<(NK * L + 255) / 256, 256>>>(phi);
    k_prep_m<<<(NK * 64 * 64 + 255) / 256, 256>>>(Mp, Mm);
    k_prep_x<<<(2 * L * 64 + 255) / 256, 256>>>(x);
    k_ar<<<(2 * L * 64) / 256, 256>>>(x, M, out);
    k_z<<<dim3(32, 2, NK), 256, ZSMEM>>>();
    k_gemm<<<dim3(16, 2, NK), 128>>>(out);
}